// round 3
// baseline (speedup 1.0000x reference)
#include <cuda_runtime.h>
#include <cuda_bf16.h>
#include <math.h>

// ---------------------------------------------------------------------------
// Problem constants
// ---------------------------------------------------------------------------
#define TSEQ 16384          // L per mamba sequence (M*N)
#define NSEQ 4              // 2 batches x 2 directions
#define TTOK 65536          // NSEQ*TSEQ
#define TOK2 32768          // output tokens (B*M*N)
#define CCH  96
#define DI   192
#define DS   16
#define NXD  38             // dtr(6) + 2*ds(32)
#define DTR  6
#define NCH  128            // scan chunks per sequence
#define LCH  128            // chunk length
#define LOG2E 1.4426950408889634f

// ---------------------------------------------------------------------------
// Scratch (static device globals; no allocation allowed)
// ---------------------------------------------------------------------------
static __device__ __align__(256) float g_cbuf  [(size_t)TTOK*CCH];
static __device__ __align__(256) float g_tcat  [(size_t)TTOK*CCH];
static __device__ __align__(256) float g_xz    [(size_t)TTOK*384];
static __device__ __align__(256) float g_xc    [(size_t)TTOK*DI];
static __device__ __align__(256) float g_xdbl  [(size_t)TTOK*NXD];
static __device__ __align__(256) float g_dt    [(size_t)TTOK*DI];
static __device__ __align__(256) float g_y     [(size_t)TTOK*DI];
static __device__ __align__(256) float g_mo    [(size_t)TTOK*CCH];
static __device__ __align__(256) float g_outssm[(size_t)TOK2*CCH];
static __device__ __align__(256) float g_lnbuf [(size_t)TOK2*CCH];
static __device__ __align__(256) float g_mid   [(size_t)TOK2*CCH];
static __device__ __align__(256) float g_hend  [NSEQ*NCH*DI*DS];
static __device__ __align__(256) float g_P     [NSEQ*NCH*DI*DS];
static __device__ __align__(256) float g_h0    [NSEQ*NCH*DI*DS];

// ---------------------------------------------------------------------------
// helpers
// ---------------------------------------------------------------------------
__device__ __forceinline__ float ex2f(float x) {
    float y;
    asm("ex2.approx.f32 %0, %1;" : "=f"(y) : "f"(x));
    return y;
}
__device__ __forceinline__ float siluf(float x) {
    return x / (1.0f + expf(-x));
}
__device__ __forceinline__ float softplusf(float x) {
    return (x > 20.0f) ? x : log1pf(expf(x));
}
__device__ __forceinline__ float geluf(float x) {
    return 0.5f * x * (1.0f + erff(x * 0.7071067811865476f));
}

// ---------------------------------------------------------------------------
// Conv 1x3 over the N dim of x (B,M,N,C), both directions.
// DIR=0: c1[n] = sum_t w[t]*x[n-1+t];  DIR=1: c2[n] = sum_t w[t]*x[n+1-t]
// Output to g_cbuf in [seq][l][c] layout, seq = DIR*2 + b, l = m*1024 + n.
// block: 256 thr; tile = 128 n-positions x 96 couts; K-loop over cin in 16s.
// ---------------------------------------------------------------------------
template <int DIR>
__global__ __launch_bounds__(256) void conv13_kernel(
    const float* __restrict__ x, const float* __restrict__ w,
    const float* __restrict__ bias)
{
    int bm = blockIdx.x >> 3;          // b*16 + m  (0..31)
    int n0 = (blockIdx.x & 7) << 7;    // n tile start (0..896)
    int b  = bm >> 4;

    __shared__ __align__(16) float As[16][136];   // As[cin][p], p = n-n0+1, 130 used
    __shared__ __align__(16) float Ws[16][292];   // Ws[cin][cout*3+tap], 288 used

    int tid = threadIdx.x;
    int tx = tid & 15;      // cout group: couts tx*6 .. tx*6+5
    int ty = tid >> 4;      // n group: n0 + ty*8 .. +7

    float acc[8][6];
#pragma unroll
    for (int i = 0; i < 8; i++)
#pragma unroll
        for (int j = 0; j < 6; j++) acc[i][j] = 0.f;

    const float* xrow = x + (size_t)bm * 1024 * CCH;

    for (int c0 = 0; c0 < CCH; c0 += 16) {
        // stage x: 130 positions x 16 cin (as 4 float4 per position)
        for (int f = tid; f < 520; f += 256) {
            int p = f >> 2, q4 = f & 3;
            int n = n0 - 1 + p;
            float4 v = make_float4(0.f, 0.f, 0.f, 0.f);
            if (n >= 0 && n < 1024)
                v = *(const float4*)&xrow[(size_t)n * CCH + c0 + q4 * 4];
            As[q4*4+0][p] = v.x; As[q4*4+1][p] = v.y;
            As[q4*4+2][p] = v.z; As[q4*4+3][p] = v.w;
        }
        // stage w tile: 96 cout x 16 cin x 3 taps
        for (int f = tid; f < 96*16*3; f += 256) {
            int cout = f / 48, r = f % 48, cin = r / 3, tap = r % 3;
            Ws[cin][cout*3 + tap] = w[((size_t)cout * CCH + (c0 + cin)) * 3 + tap];
        }
        __syncthreads();

#pragma unroll
        for (int k = 0; k < 16; k++) {
            float a[10];
            float4 a0 = *(const float4*)&As[k][ty*8];
            float4 a1 = *(const float4*)&As[k][ty*8+4];
            a[0]=a0.x; a[1]=a0.y; a[2]=a0.z; a[3]=a0.w;
            a[4]=a1.x; a[5]=a1.y; a[6]=a1.z; a[7]=a1.w;
            a[8]=As[k][ty*8+8]; a[9]=As[k][ty*8+9];
            float wv[18];
#pragma unroll
            for (int q = 0; q < 9; q++) {
                float2 t = *(const float2*)&Ws[k][tx*18 + q*2];
                wv[2*q] = t.x; wv[2*q+1] = t.y;
            }
#pragma unroll
            for (int j = 0; j < 6; j++) {
#pragma unroll
                for (int tap = 0; tap < 3; tap++) {
                    const int off = DIR ? (1 - tap) : (tap - 1);
                    float wj = wv[j*3 + tap];
#pragma unroll
                    for (int i = 0; i < 8; i++)
                        acc[i][j] = fmaf(a[1 + i + off], wj, acc[i][j]);
                }
            }
        }
        __syncthreads();
    }

    int seq = DIR * 2 + b;
    int m = bm & 15;
    size_t lbase = (size_t)seq * TSEQ + (size_t)m * 1024 + n0;
#pragma unroll
    for (int i = 0; i < 8; i++) {
        size_t row = (lbase + ty*8 + i) * CCH;
#pragma unroll
        for (int j = 0; j < 6; j++) {
            int c = tx*6 + j;
            g_cbuf[row + c] = acc[i][j] + bias[c];
        }
    }
}

// ---------------------------------------------------------------------------
// LayerNorm over 96 channels, warp per row. 256 thr = 8 rows/block.
// ---------------------------------------------------------------------------
__global__ __launch_bounds__(256) void ln_kernel(
    const float* __restrict__ in, float* __restrict__ out,
    const float* __restrict__ g, const float* __restrict__ bta, int rows)
{
    int row = blockIdx.x * 8 + (threadIdx.x >> 5);
    if (row >= rows) return;
    int lane = threadIdx.x & 31;
    const float* r = in + (size_t)row * CCH;
    float v0 = r[lane], v1 = r[lane+32], v2 = r[lane+64];
    float s = v0 + v1 + v2;
#pragma unroll
    for (int off = 16; off; off >>= 1) s += __shfl_xor_sync(0xffffffffu, s, off);
    float mu = s * (1.f/96.f);
    float d0 = v0-mu, d1 = v1-mu, d2 = v2-mu;
    float q = d0*d0 + d1*d1 + d2*d2;
#pragma unroll
    for (int off = 16; off; off >>= 1) q += __shfl_xor_sync(0xffffffffu, q, off);
    float rs = rsqrtf(q * (1.f/96.f) + 1e-5f);
    float* o = out + (size_t)row * CCH;
    o[lane]    = d0 * rs * g[lane]    + bta[lane];
    o[lane+32] = d1 * rs * g[lane+32] + bta[lane+32];
    o[lane+64] = d2 * rs * g[lane+64] + bta[lane+64];
}

// ---------------------------------------------------------------------------
// SGEMM: out[M,N] = act(A[M,K] @ W[N,K]^T + bias) + res
// BM=128, BN=96, BK=16. 256 threads, 8x6 microtile. M%128==0, K%16==0.
// ACT: 0=none, 1=gelu.
// ---------------------------------------------------------------------------
template <int ACT, bool HASB, bool HASR>
__global__ __launch_bounds__(256) void sgemm_kernel(
    const float* __restrict__ A, const float* __restrict__ W,
    const float* __restrict__ bias, const float* __restrict__ res,
    float* __restrict__ out, int M, int N, int K)
{
    __shared__ __align__(16) float As[16][132];   // As[k][m]
    __shared__ __align__(16) float Ws[16][100];   // Ws[k][n]
    int tid = threadIdx.x, tx = tid & 15, ty = tid >> 4;
    int m0 = blockIdx.x * 128, n0 = blockIdx.y * 96;

    float acc[8][6];
#pragma unroll
    for (int i = 0; i < 8; i++)
#pragma unroll
        for (int j = 0; j < 6; j++) acc[i][j] = 0.f;

    for (int k0 = 0; k0 < K; k0 += 16) {
        // stage A tile: 128 x 16 = 512 float4
#pragma unroll
        for (int it = 0; it < 2; it++) {
            int f = tid + it * 256;
            int m = f >> 2, q = f & 3;
            float4 v = *(const float4*)&A[(size_t)(m0 + m) * K + k0 + q*4];
            As[q*4+0][m] = v.x; As[q*4+1][m] = v.y;
            As[q*4+2][m] = v.z; As[q*4+3][m] = v.w;
        }
        // stage W tile: 96 x 16 = 384 float4 (guard n)
        for (int f = tid; f < 384; f += 256) {
            int n = f >> 2, q = f & 3;
            float4 v = make_float4(0.f,0.f,0.f,0.f);
            if (n0 + n < N)
                v = *(const float4*)&W[(size_t)(n0 + n) * K + k0 + q*4];
            Ws[q*4+0][n] = v.x; Ws[q*4+1][n] = v.y;
            Ws[q*4+2][n] = v.z; Ws[q*4+3][n] = v.w;
        }
        __syncthreads();

#pragma unroll
        for (int k = 0; k < 16; k++) {
            float a[8];
            float4 a0 = *(const float4*)&As[k][ty*8];
            float4 a1 = *(const float4*)&As[k][ty*8+4];
            a[0]=a0.x; a[1]=a0.y; a[2]=a0.z; a[3]=a0.w;
            a[4]=a1.x; a[5]=a1.y; a[6]=a1.z; a[7]=a1.w;
            float wv[6];
#pragma unroll
            for (int q = 0; q < 3; q++) {
                float2 t = *(const float2*)&Ws[k][tx*6 + q*2];
                wv[2*q] = t.x; wv[2*q+1] = t.y;
            }
#pragma unroll
            for (int i = 0; i < 8; i++)
#pragma unroll
                for (int j = 0; j < 6; j++)
                    acc[i][j] = fmaf(a[i], wv[j], acc[i][j]);
        }
        __syncthreads();
    }

#pragma unroll
    for (int i = 0; i < 8; i++) {
        size_t row = (size_t)(m0 + ty*8 + i) * N;
#pragma unroll
        for (int j = 0; j < 6; j++) {
            int n = n0 + tx*6 + j;
            if (n < N) {
                float v = acc[i][j];
                if (HASB) v += bias[n];
                if (ACT == 1) v = geluf(v);
                if (HASR) v += res[row + n];
                out[row + n] = v;
            }
        }
    }
}

// ---------------------------------------------------------------------------
// Depthwise causal conv1d (k=4) + bias + silu. xm = cols [0,192) of g_xz.
// ---------------------------------------------------------------------------
__global__ __launch_bounds__(256) void conv1d_kernel(
    const float* __restrict__ xz, const float* __restrict__ w,
    const float* __restrict__ b)
{
    int idx = blockIdx.x * 256 + threadIdx.x;     // tok*192 + d
    int tok = idx / DI, d = idx - tok * DI;
    int pos = tok & (TSEQ - 1);
    float acc = b[d];
#pragma unroll
    for (int t = 0; t < 4; t++) {
        int p = pos - 3 + t;
        if (p >= 0)
            acc = fmaf(w[d*4 + t], xz[(size_t)(tok - 3 + t) * 384 + d], acc);
    }
    g_xc[(size_t)tok * DI + d] = siluf(acc);
}

// ---------------------------------------------------------------------------
// dt = softplus(x_dbl[:, :6] @ dt_proj_w^T + dt_proj_b)
// ---------------------------------------------------------------------------
__global__ __launch_bounds__(256) void dt_kernel(
    const float* __restrict__ dtw, const float* __restrict__ dtb)
{
    int idx = blockIdx.x * 256 + threadIdx.x;
    int tok = idx / DI, d = idx - tok * DI;
    const float* xr = &g_xdbl[(size_t)tok * NXD];
    float acc = dtb[d];
#pragma unroll
    for (int r = 0; r < DTR; r++)
        acc = fmaf(dtw[d*DTR + r], xr[r], acc);
    g_dt[(size_t)tok * DI + d] = softplusf(acc);
}

// ---------------------------------------------------------------------------
// Scan S1: per (seq,chunk) block of 192 threads (one per d).
// Local scan from h=0 -> hend; chunk decay P = exp(A * sum(dt)).
// ---------------------------------------------------------------------------
__global__ __launch_bounds__(192) void scan1_kernel(const float* __restrict__ A_log)
{
    int seq = blockIdx.x >> 7, ch = blockIdx.x & 127;
    int d = threadIdx.x;
    int tok0 = seq * TSEQ + ch * LCH;

    __shared__ __align__(16) float Bs[LCH][DS];
    for (int f = d; f < LCH*DS; f += 192) {
        int l = f >> 4, s = f & 15;
        Bs[l][s] = g_xdbl[(size_t)(tok0 + l) * NXD + DTR + s];
    }
    __syncthreads();

    float aa[DS], h[DS];
#pragma unroll
    for (int s = 0; s < DS; s++) {
        aa[s] = -expf(A_log[d*DS + s]) * LOG2E;
        h[s] = 0.f;
    }
    float dtsum = 0.f;

    for (int l = 0; l < LCH; l++) {
        int tok = tok0 + l;
        float dt = g_dt[(size_t)tok * DI + d];
        float u  = g_xc[(size_t)tok * DI + d];
        float du = dt * u;
        dtsum += dt;
        float bl[DS];
#pragma unroll
        for (int q = 0; q < 4; q++) {
            float4 v = *(const float4*)&Bs[l][q*4];
            bl[q*4]=v.x; bl[q*4+1]=v.y; bl[q*4+2]=v.z; bl[q*4+3]=v.w;
        }
#pragma unroll
        for (int s = 0; s < DS; s++) {
            float e = ex2f(aa[s] * dt);
            h[s] = fmaf(e, h[s], du * bl[s]);
        }
    }
    size_t base = ((size_t)(seq*NCH + ch) * DI + d) * DS;
#pragma unroll
    for (int s = 0; s < DS; s++) {
        g_hend[base + s] = h[s];
        g_P[base + s]    = ex2f(aa[s] * dtsum);
    }
}

// ---------------------------------------------------------------------------
// Scan S2: sequential cross-chunk combine; thread per (seq,d,s). 12288 threads.
// h0[c] = state entering chunk c; H_c = hend_c + P_c * H_{c-1}
// ---------------------------------------------------------------------------
__global__ __launch_bounds__(256) void scan2_kernel()
{
    int idx = blockIdx.x * 256 + threadIdx.x;     // seq*3072 + d*16 + s
    int seq = idx / (DI*DS), ds_ = idx - seq * (DI*DS);
    float H = 0.f;
    for (int c = 0; c < NCH; c++) {
        size_t base = (size_t)(seq*NCH + c) * (DI*DS) + ds_;
        g_h0[base] = H;
        H = fmaf(g_P[base], H, g_hend[base]);
    }
}

// ---------------------------------------------------------------------------
// Scan S3: recompute local scan with initial state h0, emit
// yg = (y + u*Dp) * silu(z)  into g_y.
// ---------------------------------------------------------------------------
__global__ __launch_bounds__(192) void scan3_kernel(
    const float* __restrict__ A_log, const float* __restrict__ Dp)
{
    int seq = blockIdx.x >> 7, ch = blockIdx.x & 127;
    int d = threadIdx.x;
    int tok0 = seq * TSEQ + ch * LCH;

    __shared__ __align__(16) float Bs[LCH][DS];
    __shared__ __align__(16) float Cs[LCH][DS];
    for (int f = d; f < LCH*DS; f += 192) {
        int l = f >> 4, s = f & 15;
        size_t r = (size_t)(tok0 + l) * NXD + DTR;
        Bs[l][s] = g_xdbl[r + s];
        Cs[l][s] = g_xdbl[r + DS + s];
    }
    __syncthreads();

    float aa[DS], h[DS];
    size_t base = ((size_t)(seq*NCH + ch) * DI + d) * DS;
#pragma unroll
    for (int s = 0; s < DS; s++) {
        aa[s] = -expf(A_log[d*DS + s]) * LOG2E;
        h[s] = g_h0[base + s];
    }
    float dval = Dp[d];

    for (int l = 0; l < LCH; l++) {
        int tok = tok0 + l;
        float dt = g_dt[(size_t)tok * DI + d];
        float u  = g_xc[(size_t)tok * DI + d];
        float du = dt * u;
        float bl[DS], cl[DS];
#pragma unroll
        for (int q = 0; q < 4; q++) {
            float4 v = *(const float4*)&Bs[l][q*4];
            bl[q*4]=v.x; bl[q*4+1]=v.y; bl[q*4+2]=v.z; bl[q*4+3]=v.w;
            float4 c = *(const float4*)&Cs[l][q*4];
            cl[q*4]=c.x; cl[q*4+1]=c.y; cl[q*4+2]=c.z; cl[q*4+3]=c.w;
        }
        float y = 0.f;
#pragma unroll
        for (int s = 0; s < DS; s++) {
            float e = ex2f(aa[s] * dt);
            h[s] = fmaf(e, h[s], du * bl[s]);
            y = fmaf(h[s], cl[s], y);
        }
        y = fmaf(u, dval, y);
        float z = g_xz[(size_t)tok * 384 + DI + d];
        g_y[(size_t)tok * DI + d] = y * siluf(z);
    }
}

// ---------------------------------------------------------------------------
// out_ssm[t] = mo[t] + mo[t+32768] + tcat[t] + tcat[t+32768]
// (seq 0,1 = t1 batches; seq 2,3 = t2 batches; row b*16384+l == t)
// ---------------------------------------------------------------------------
__global__ __launch_bounds__(256) void combine_kernel()
{
    size_t idx = (size_t)blockIdx.x * 256 + threadIdx.x;  // t*96 + c
    size_t hi = idx + (size_t)TOK2 * CCH;
    g_outssm[idx] = g_mo[idx] + g_mo[hi] + g_tcat[idx] + g_tcat[hi];
}

// ---------------------------------------------------------------------------
extern "C" void kernel_launch(void* const* d_in, const int* in_sizes, int n_in,
                              void* d_out, int out_size) {
    const float* x          = (const float*)d_in[0];
    const float* conv1234_w = (const float*)d_in[1];
    const float* conv1234_b = (const float*)d_in[2];
    const float* conv4321_w = (const float*)d_in[3];
    const float* conv4321_b = (const float*)d_in[4];
    const float* ln_g       = (const float*)d_in[5];
    const float* ln_b       = (const float*)d_in[6];
    const float* in_proj_w  = (const float*)d_in[7];
    const float* conv1d_w   = (const float*)d_in[8];
    const float* conv1d_b   = (const float*)d_in[9];
    const float* x_proj_w   = (const float*)d_in[10];
    const float* dt_proj_w  = (const float*)d_in[11];
    const float* dt_proj_b  = (const float*)d_in[12];
    const float* A_log      = (const float*)d_in[13];
    const float* Dp         = (const float*)d_in[14];
    const float* out_proj_w = (const float*)d_in[15];
    const float* fc1_w      = (const float*)d_in[16];
    const float* fc1_b      = (const float*)d_in[17];
    const float* fc2_w      = (const float*)d_in[18];
    const float* fc2_b      = (const float*)d_in[19];
    float* out = (float*)d_out;

    float *cbuf, *tcat, *xz, *xc, *xdbl, *dt, *y, *mo, *outssm, *lnbuf, *mid;
    cudaGetSymbolAddress((void**)&cbuf,   g_cbuf);
    cudaGetSymbolAddress((void**)&tcat,   g_tcat);
    cudaGetSymbolAddress((void**)&xz,     g_xz);
    cudaGetSymbolAddress((void**)&xc,     g_xc);
    cudaGetSymbolAddress((void**)&xdbl,   g_xdbl);
    cudaGetSymbolAddress((void**)&dt,     g_dt);
    cudaGetSymbolAddress((void**)&y,      g_y);
    cudaGetSymbolAddress((void**)&mo,     g_mo);
    cudaGetSymbolAddress((void**)&outssm, g_outssm);
    cudaGetSymbolAddress((void**)&lnbuf,  g_lnbuf);
    cudaGetSymbolAddress((void**)&mid,    g_mid);

    // 1) conv 1x3 both directions -> g_cbuf [4 seqs][16384][96]
    conv13_kernel<0><<<256, 256>>>(x, conv1234_w, conv1234_b);
    conv13_kernel<1><<<256, 256>>>(x, conv4321_w, conv4321_b);

    // 2) LN -> g_tcat (t1 stacked with t2, 65536 rows)
    ln_kernel<<<TTOK/8, 256>>>(cbuf, tcat, ln_g, ln_b, TTOK);

    // 3) in_proj: [65536,96] @ [384,96]^T -> g_xz
    {
        dim3 grid(TTOK/128, 4);
        sgemm_kernel<0,false,false><<<grid, 256>>>(tcat, in_proj_w, nullptr, nullptr, xz, TTOK, 384, CCH);
    }

    // 4) depthwise conv1d + silu -> g_xc
    conv1d_kernel<<<(TTOK*DI)/256, 256>>>(xz, conv1d_w, conv1d_b);

    // 5) x_proj: [65536,192] @ [38,192]^T -> g_xdbl
    {
        dim3 grid(TTOK/128, 1);
        sgemm_kernel<0,false,false><<<grid, 256>>>(xc, x_proj_w, nullptr, nullptr, xdbl, TTOK, NXD, DI);
    }

    // 6) dt projection + softplus -> g_dt
    dt_kernel<<<(TTOK*DI)/256, 256>>>(dt_proj_w, dt_proj_b);

    // 7-9) chunked selective scan
    scan1_kernel<<<NSEQ*NCH, 192>>>(A_log);
    scan2_kernel<<<(NSEQ*DI*DS)/256, 256>>>();
    scan3_kernel<<<NSEQ*NCH, 192>>>(A_log, Dp);

    // 10) out_proj: [65536,192] @ [96,192]^T -> g_mo
    {
        dim3 grid(TTOK/128, 1);
        sgemm_kernel<0,false,false><<<grid, 256>>>(y, out_proj_w, nullptr, nullptr, mo, TTOK, CCH, DI);
    }

    // 11) out_ssm = mamba(t1)+mamba(t2)+t1+t2
    combine_kernel<<<(TOK2*CCH)/256, 256>>>();

    // 12) LN -> g_lnbuf
    ln_kernel<<<TOK2/8, 256>>>(outssm, lnbuf, ln_g, ln_b, TOK2);

    // 13) fc1 + gelu -> g_mid
    {
        dim3 grid(TOK2/128, 1);
        sgemm_kernel<1,true,false><<<grid, 256>>>(lnbuf, fc1_w, fc1_b, nullptr, mid, TOK2, CCH, CCH);
    }

    // 14) fc2 + bias + residual(out_ssm) -> d_out
    {
        dim3 grid(TOK2/128, 1);
        sgemm_kernel<0,true,true><<<grid, 256>>>(mid, fc2_w, fc2_b, outssm, out, TOK2, CCH, CCH);
    }
}

// round 5
// speedup vs baseline: 1.3048x; 1.3048x over previous
#include <cuda_runtime.h>
#include <cuda_bf16.h>
#include <math.h>

// ---------------------------------------------------------------------------
// Problem constants
// ---------------------------------------------------------------------------
#define TSEQ 16384          // L per mamba sequence (M*N)
#define NSEQ 4              // 2 batches x 2 directions
#define TTOK 65536          // NSEQ*TSEQ
#define TOK2 32768          // output tokens (B*M*N)
#define CCH  96
#define DI   192
#define DS   16
#define NXD  38             // dtr(6) + 2*ds(32)
#define DTR  6
#define NCH  128            // scan chunks per sequence
#define LCH  128            // chunk length
#define LOG2E 1.4426950408889634f

// ---------------------------------------------------------------------------
// Scratch (static device globals; no allocation allowed)
// ---------------------------------------------------------------------------
static __device__ __align__(256) float g_cbuf  [(size_t)TTOK*CCH];
static __device__ __align__(256) float g_tcat  [(size_t)TTOK*CCH];
static __device__ __align__(256) float g_xz    [(size_t)TTOK*384];
static __device__ __align__(256) float g_xc    [(size_t)TTOK*DI];
static __device__ __align__(256) float g_xdbl  [(size_t)TTOK*NXD];
static __device__ __align__(256) float g_dt    [(size_t)TTOK*DI];
static __device__ __align__(256) float g_y     [(size_t)TTOK*DI];
static __device__ __align__(256) float g_mo    [(size_t)TTOK*CCH];
static __device__ __align__(256) float g_outssm[(size_t)TOK2*CCH];
static __device__ __align__(256) float g_lnbuf [(size_t)TOK2*CCH];
static __device__ __align__(256) float g_mid   [(size_t)TOK2*CCH];
static __device__ __align__(256) float g_hend  [NSEQ*NCH*DI*DS];
static __device__ __align__(256) float g_P     [NSEQ*NCH*DI*DS];
static __device__ __align__(256) float g_h0    [NSEQ*NCH*DI*DS];

// ---------------------------------------------------------------------------
// helpers
// ---------------------------------------------------------------------------
__device__ __forceinline__ float ex2f(float x) {
    float y;
    asm("ex2.approx.f32 %0, %1;" : "=f"(y) : "f"(x));
    return y;
}
__device__ __forceinline__ float siluf(float x) {
    return x / (1.0f + expf(-x));
}
__device__ __forceinline__ float softplusf(float x) {
    return (x > 20.0f) ? x : log1pf(expf(x));
}
__device__ __forceinline__ float geluf(float x) {
    return 0.5f * x * (1.0f + erff(x * 0.7071067811865476f));
}
__device__ __forceinline__ unsigned f2tf(float x) {
    unsigned r;
    asm("cvt.rna.tf32.f32 %0, %1;" : "=r"(r) : "f"(x));
    return r;
}
// D += A(16x8,row) * B(8x8,col) tf32
__device__ __forceinline__ void mma8(float* c, const unsigned* a,
                                     unsigned b0, unsigned b1) {
    asm volatile(
        "mma.sync.aligned.m16n8k8.row.col.f32.tf32.tf32.f32 "
        "{%0,%1,%2,%3}, {%4,%5,%6,%7}, {%8,%9}, {%0,%1,%2,%3};"
        : "+f"(c[0]), "+f"(c[1]), "+f"(c[2]), "+f"(c[3])
        : "r"(a[0]), "r"(a[1]), "r"(a[2]), "r"(a[3]), "r"(b0), "r"(b1));
}

// ---------------------------------------------------------------------------
// TF32 GEMM: out[M,N] = act(A[M,K] @ W[N,K]^T + bias) + res
// BM=128, BN=96, BK=16. 8 warps, warp tile 32x48 (2 m-frags x 6 n-frags).
// M%128==0, K%16==0. ACT: 0=none, 1=gelu.
// ---------------------------------------------------------------------------
template <int ACT, bool HASB, bool HASR>
__global__ __launch_bounds__(256) void gemm_tf32_kernel(
    const float* __restrict__ A, const float* __restrict__ W,
    const float* __restrict__ bias, const float* __restrict__ res,
    float* __restrict__ out, int M, int N, int K)
{
    __shared__ unsigned As[16][136];   // As[k][m], stride 136 (8 mod 32)
    __shared__ unsigned Ws[16][104];   // Ws[k][n], stride 104 (8 mod 32)

    int tid = threadIdx.x, lane = tid & 31, warp = tid >> 5;
    int wm = warp >> 1, wn = warp & 1;
    int qr = lane >> 2, qc = lane & 3;
    int m0 = blockIdx.x * 128, n0 = blockIdx.y * 96;

    float acc[2][6][4];
#pragma unroll
    for (int i = 0; i < 2; i++)
#pragma unroll
        for (int j = 0; j < 6; j++)
#pragma unroll
            for (int q = 0; q < 4; q++) acc[i][j][q] = 0.f;

    for (int k0 = 0; k0 < K; k0 += 16) {
        // stage A: 128 rows x 16 k (512 float4)
#pragma unroll
        for (int it = 0; it < 2; it++) {
            int f = tid + it * 256;
            int m = f >> 2, q = f & 3;
            float4 v = *(const float4*)&A[(size_t)(m0 + m) * K + k0 + q * 4];
            As[q*4+0][m] = f2tf(v.x); As[q*4+1][m] = f2tf(v.y);
            As[q*4+2][m] = f2tf(v.z); As[q*4+3][m] = f2tf(v.w);
        }
        // stage W: 96 rows x 16 k (384 float4), guard n<N
        for (int f = tid; f < 384; f += 256) {
            int n = f >> 2, q = f & 3;
            float4 v = make_float4(0.f, 0.f, 0.f, 0.f);
            if (n0 + n < N)
                v = *(const float4*)&W[(size_t)(n0 + n) * K + k0 + q * 4];
            Ws[q*4+0][n] = f2tf(v.x); Ws[q*4+1][n] = f2tf(v.y);
            Ws[q*4+2][n] = f2tf(v.z); Ws[q*4+3][n] = f2tf(v.w);
        }
        __syncthreads();

#pragma unroll
        for (int ks = 0; ks < 2; ks++) {
            int kb = ks * 8;
            unsigned a[2][4];
#pragma unroll
            for (int mt = 0; mt < 2; mt++) {
                int r = wm * 32 + mt * 16 + qr;
                a[mt][0] = As[kb + qc][r];
                a[mt][1] = As[kb + qc][r + 8];
                a[mt][2] = As[kb + qc + 4][r];
                a[mt][3] = As[kb + qc + 4][r + 8];
            }
#pragma unroll
            for (int nt = 0; nt < 6; nt++) {
                int cn = wn * 48 + nt * 8 + qr;
                unsigned b0 = Ws[kb + qc][cn];
                unsigned b1 = Ws[kb + qc + 4][cn];
                mma8(acc[0][nt], a[0], b0, b1);
                mma8(acc[1][nt], a[1], b0, b1);
            }
        }
        __syncthreads();
    }

    // epilogue
#pragma unroll
    for (int mt = 0; mt < 2; mt++) {
        int r = m0 + wm * 32 + mt * 16 + qr;
#pragma unroll
        for (int nt = 0; nt < 6; nt++) {
            int c = n0 + wn * 48 + nt * 8 + 2 * qc;
            if (c >= N) continue;
            bool two = (c + 1 < N);
            float b0v = HASB ? bias[c] : 0.f;
            float b1v = (HASB && two) ? bias[c + 1] : 0.f;
            size_t ro0 = (size_t)r * N, ro1 = (size_t)(r + 8) * N;
            float v00 = acc[mt][nt][0] + b0v;
            float v01 = acc[mt][nt][1] + b1v;
            float v10 = acc[mt][nt][2] + b0v;
            float v11 = acc[mt][nt][3] + b1v;
            if (ACT == 1) { v00 = geluf(v00); v01 = geluf(v01);
                            v10 = geluf(v10); v11 = geluf(v11); }
            if (HASR) {
                v00 += res[ro0 + c]; v10 += res[ro1 + c];
                if (two) { v01 += res[ro0 + c + 1]; v11 += res[ro1 + c + 1]; }
            }
            out[ro0 + c] = v00;
            out[ro1 + c] = v10;
            if (two) { out[ro0 + c + 1] = v01; out[ro1 + c + 1] = v11; }
        }
    }
}

// ---------------------------------------------------------------------------
// Conv 1x3 over the N dim via tf32 MMA (3 shifted-A matmuls).
// DIR=0: c1[n] = sum_t w[t]*x[n-1+t];  DIR=1: c2[n] = sum_t w[t]*x[n+1-t]
// Output g_cbuf [seq][l][c], seq = DIR*2 + b, l = m*1024 + n.
// Block: 128 n-positions x 96 couts; K-loop over cin (6 x 16).
// ---------------------------------------------------------------------------
template <int DIR>
__global__ __launch_bounds__(256) void conv13_mma_kernel(
    const float* __restrict__ x, const float* __restrict__ w,
    const float* __restrict__ bias)
{
    int bm = blockIdx.x >> 3;          // b*16 + m  (0..31)
    int n0 = (blockIdx.x & 7) << 7;    // n tile start (0..896)
    int b  = bm >> 4, m_img = bm & 15;

    __shared__ unsigned As[16][136];       // As[cin][p], p = n-n0+1 (130 used)
    __shared__ unsigned Ws3[3][16][104];   // Ws3[tap][cin][cout]

    int tid = threadIdx.x, lane = tid & 31, warp = tid >> 5;
    int wm = warp >> 1, wn = warp & 1;
    int qr = lane >> 2, qc = lane & 3;

    float acc[2][6][4];
#pragma unroll
    for (int i = 0; i < 2; i++)
#pragma unroll
        for (int j = 0; j < 6; j++)
#pragma unroll
            for (int q = 0; q < 4; q++) acc[i][j][q] = 0.f;

    const float* xrow = x + (size_t)bm * 1024 * CCH;

    for (int c0 = 0; c0 < CCH; c0 += 16) {
        // stage x: 130 positions x 16 cin
        for (int f = tid; f < 520; f += 256) {
            int p = f >> 2, q = f & 3;
            int n = n0 - 1 + p;
            float4 v = make_float4(0.f, 0.f, 0.f, 0.f);
            if (n >= 0 && n < 1024)
                v = *(const float4*)&xrow[(size_t)n * CCH + c0 + q * 4];
            As[q*4+0][p] = f2tf(v.x); As[q*4+1][p] = f2tf(v.y);
            As[q*4+2][p] = f2tf(v.z); As[q*4+3][p] = f2tf(v.w);
        }
        // stage w: 3 taps x 16 cin x 96 cout
        for (int f = tid; f < 4608; f += 256) {
            int tap = f / 1536, r = f - tap * 1536;
            int k = r / 96, cout = r - k * 96;
            Ws3[tap][k][cout] =
                f2tf(w[((size_t)cout * CCH + (c0 + k)) * 3 + tap]);
        }
        __syncthreads();

#pragma unroll
        for (int ks = 0; ks < 2; ks++) {
            int kb = ks * 8;
#pragma unroll
            for (int tap = 0; tap < 3; tap++) {
                const int off = DIR ? (1 - tap) : (tap - 1);
                unsigned a[2][4];
#pragma unroll
                for (int mt = 0; mt < 2; mt++) {
                    int r = wm * 32 + mt * 16 + qr + 1 + off;
                    a[mt][0] = As[kb + qc][r];
                    a[mt][1] = As[kb + qc][r + 8];
                    a[mt][2] = As[kb + qc + 4][r];
                    a[mt][3] = As[kb + qc + 4][r + 8];
                }
#pragma unroll
                for (int nt = 0; nt < 6; nt++) {
                    int cn = wn * 48 + nt * 8 + qr;
                    unsigned b0 = Ws3[tap][kb + qc][cn];
                    unsigned b1 = Ws3[tap][kb + qc + 4][cn];
                    mma8(acc[0][nt], a[0], b0, b1);
                    mma8(acc[1][nt], a[1], b0, b1);
                }
            }
        }
        __syncthreads();
    }

    int seq = DIR * 2 + b;
    size_t lbase = (size_t)seq * TSEQ + (size_t)m_img * 1024 + n0;
#pragma unroll
    for (int mt = 0; mt < 2; mt++) {
        int tr = wm * 32 + mt * 16 + qr;
        size_t ro0 = (lbase + tr) * CCH;
        size_t ro1 = (lbase + tr + 8) * CCH;
#pragma unroll
        for (int nt = 0; nt < 6; nt++) {
            int c = wn * 48 + nt * 8 + 2 * qc;
            float bc0 = bias[c], bc1 = bias[c + 1];
            float2 s0 = make_float2(acc[mt][nt][0] + bc0, acc[mt][nt][1] + bc1);
            float2 s1 = make_float2(acc[mt][nt][2] + bc0, acc[mt][nt][3] + bc1);
            *(float2*)&g_cbuf[ro0 + c] = s0;
            *(float2*)&g_cbuf[ro1 + c] = s1;
        }
    }
}

// ---------------------------------------------------------------------------
// LayerNorm over 96 channels, warp per row. 256 thr = 8 rows/block.
// ---------------------------------------------------------------------------
__global__ __launch_bounds__(256) void ln_kernel(
    const float* __restrict__ in, float* __restrict__ out,
    const float* __restrict__ g, const float* __restrict__ bta, int rows)
{
    int row = blockIdx.x * 8 + (threadIdx.x >> 5);
    if (row >= rows) return;
    int lane = threadIdx.x & 31;
    const float* r = in + (size_t)row * CCH;
    float v0 = r[lane], v1 = r[lane+32], v2 = r[lane+64];
    float s = v0 + v1 + v2;
#pragma unroll
    for (int off = 16; off; off >>= 1) s += __shfl_xor_sync(0xffffffffu, s, off);
    float mu = s * (1.f/96.f);
    float d0 = v0-mu, d1 = v1-mu, d2 = v2-mu;
    float q = d0*d0 + d1*d1 + d2*d2;
#pragma unroll
    for (int off = 16; off; off >>= 1) q += __shfl_xor_sync(0xffffffffu, q, off);
    float rs = rsqrtf(q * (1.f/96.f) + 1e-5f);
    float* o = out + (size_t)row * CCH;
    o[lane]    = d0 * rs * g[lane]    + bta[lane];
    o[lane+32] = d1 * rs * g[lane+32] + bta[lane+32];
    o[lane+64] = d2 * rs * g[lane+64] + bta[lane+64];
}

// ---------------------------------------------------------------------------
// Depthwise causal conv1d (k=4) + bias + silu. xm = cols [0,192) of g_xz.
// ---------------------------------------------------------------------------
__global__ __launch_bounds__(256) void conv1d_kernel(
    const float* __restrict__ xz, const float* __restrict__ w,
    const float* __restrict__ b)
{
    int idx = blockIdx.x * 256 + threadIdx.x;     // tok*192 + d
    int tok = idx / DI, d = idx - tok * DI;
    int pos = tok & (TSEQ - 1);
    float acc = b[d];
#pragma unroll
    for (int t = 0; t < 4; t++) {
        int p = pos - 3 + t;
        if (p >= 0)
            acc = fmaf(w[d*4 + t], xz[(size_t)(tok - 3 + t) * 384 + d], acc);
    }
    g_xc[(size_t)tok * DI + d] = siluf(acc);
}

// ---------------------------------------------------------------------------
// dt = softplus(x_dbl[:, :6] @ dt_proj_w^T + dt_proj_b)
// ---------------------------------------------------------------------------
__global__ __launch_bounds__(256) void dt_kernel(
    const float* __restrict__ dtw, const float* __restrict__ dtb)
{
    int idx = blockIdx.x * 256 + threadIdx.x;
    int tok = idx / DI, d = idx - tok * DI;
    const float* xr = &g_xdbl[(size_t)tok * NXD];
    float acc = dtb[d];
#pragma unroll
    for (int r = 0; r < DTR; r++)
        acc = fmaf(dtw[d*DTR + r], xr[r], acc);
    g_dt[(size_t)tok * DI + d] = softplusf(acc);
}

// ---------------------------------------------------------------------------
// Scan S1: per (seq,chunk) block of 192 threads (one per d).
// Local scan from h=0 -> hend; chunk decay P = exp(A * sum(dt)).
// ---------------------------------------------------------------------------
__global__ __launch_bounds__(192) void scan1_kernel(const float* __restrict__ A_log)
{
    int seq = blockIdx.x >> 7, ch = blockIdx.x & 127;
    int d = threadIdx.x;
    int tok0 = seq * TSEQ + ch * LCH;

    __shared__ __align__(16) float Bs[LCH][DS];
    for (int f = d; f < LCH*DS; f += 192) {
        int l = f >> 4, s = f & 15;
        Bs[l][s] = g_xdbl[(size_t)(tok0 + l) * NXD + DTR + s];
    }
    __syncthreads();

    float aa[DS], h[DS];
#pragma unroll
    for (int s = 0; s < DS; s++) {
        aa[s] = -expf(A_log[d*DS + s]) * LOG2E;
        h[s] = 0.f;
    }
    float dtsum = 0.f;

    for (int l = 0; l < LCH; l++) {
        int tok = tok0 + l;
        float dt = g_dt[(size_t)tok * DI + d];
        float u  = g_xc[(size_t)tok * DI + d];
        float du = dt * u;
        dtsum += dt;
        float bl[DS];
#pragma unroll
        for (int q = 0; q < 4; q++) {
            float4 v = *(const float4*)&Bs[l][q*4];
            bl[q*4]=v.x; bl[q*4+1]=v.y; bl[q*4+2]=v.z; bl[q*4+3]=v.w;
        }
#pragma unroll
        for (int s = 0; s < DS; s++) {
            float e = ex2f(aa[s] * dt);
            h[s] = fmaf(e, h[s], du * bl[s]);
        }
    }
    size_t base = ((size_t)(seq*NCH + ch) * DI + d) * DS;
#pragma unroll
    for (int s = 0; s < DS; s++) {
        g_hend[base + s] = h[s];
        g_P[base + s]    = ex2f(aa[s] * dtsum);
    }
}

// ---------------------------------------------------------------------------
// Scan S2: sequential cross-chunk combine; thread per (seq,d,s).
// ---------------------------------------------------------------------------
__global__ __launch_bounds__(256) void scan2_kernel()
{
    int idx = blockIdx.x * 256 + threadIdx.x;     // seq*3072 + d*16 + s
    int seq = idx / (DI*DS), ds_ = idx - seq * (DI*DS);
    float H = 0.f;
    for (int c = 0; c < NCH; c++) {
        size_t base = (size_t)(seq*NCH + c) * (DI*DS) + ds_;
        g_h0[base] = H;
        H = fmaf(g_P[base], H, g_hend[base]);
    }
}

// ---------------------------------------------------------------------------
// Scan S3: recompute local scan with initial state h0, emit
// yg = (y + u*Dp) * silu(z)  into g_y.
// ---------------------------------------------------------------------------
__global__ __launch_bounds__(192) void scan3_kernel(
    const float* __restrict__ A_log, const float* __restrict__ Dp)
{
    int seq = blockIdx.x >> 7, ch = blockIdx.x & 127;
    int d = threadIdx.x;
    int tok0 = seq * TSEQ + ch * LCH;

    __shared__ __align__(16) float Bs[LCH][DS];
    __shared__ __align__(16) float Cs[LCH][DS];
    for (int f = d; f < LCH*DS; f += 192) {
        int l = f >> 4, s = f & 15;
        size_t r = (size_t)(tok0 + l) * NXD + DTR;
        Bs[l][s] = g_xdbl[r + s];
        Cs[l][s] = g_xdbl[r + DS + s];
    }
    __syncthreads();

    float aa[DS], h[DS];
    size_t base = ((size_t)(seq*NCH + ch) * DI + d) * DS;
#pragma unroll
    for (int s = 0; s < DS; s++) {
        aa[s] = -expf(A_log[d*DS + s]) * LOG2E;
        h[s] = g_h0[base + s];
    }
    float dval = Dp[d];

    for (int l = 0; l < LCH; l++) {
        int tok = tok0 + l;
        float dt = g_dt[(size_t)tok * DI + d];
        float u  = g_xc[(size_t)tok * DI + d];
        float du = dt * u;
        float bl[DS], cl[DS];
#pragma unroll
        for (int q = 0; q < 4; q++) {
            float4 v = *(const float4*)&Bs[l][q*4];
            bl[q*4]=v.x; bl[q*4+1]=v.y; bl[q*4+2]=v.z; bl[q*4+3]=v.w;
            float4 c = *(const float4*)&Cs[l][q*4];
            cl[q*4]=c.x; cl[q*4+1]=c.y; cl[q*4+2]=c.z; cl[q*4+3]=c.w;
        }
        float y = 0.f;
#pragma unroll
        for (int s = 0; s < DS; s++) {
            float e = ex2f(aa[s] * dt);
            h[s] = fmaf(e, h[s], du * bl[s]);
            y = fmaf(h[s], cl[s], y);
        }
        y = fmaf(u, dval, y);
        float z = g_xz[(size_t)tok * 384 + DI + d];
        g_y[(size_t)tok * DI + d] = y * siluf(z);
    }
}

// ---------------------------------------------------------------------------
// out_ssm[t] = mo[t] + mo[t+32768] + tcat[t] + tcat[t+32768]
// ---------------------------------------------------------------------------
__global__ __launch_bounds__(256) void combine_kernel()
{
    size_t idx = (size_t)blockIdx.x * 256 + threadIdx.x;  // t*96 + c
    size_t hi = idx + (size_t)TOK2 * CCH;
    g_outssm[idx] = g_mo[idx] + g_mo[hi] + g_tcat[idx] + g_tcat[hi];
}

// ---------------------------------------------------------------------------
extern "C" void kernel_launch(void* const* d_in, const int* in_sizes, int n_in,
                              void* d_out, int out_size) {
    const float* x          = (const float*)d_in[0];
    const float* conv1234_w = (const float*)d_in[1];
    const float* conv1234_b = (const float*)d_in[2];
    const float* conv4321_w = (const float*)d_in[3];
    const float* conv4321_b = (const float*)d_in[4];
    const float* ln_g       = (const float*)d_in[5];
    const float* ln_b       = (const float*)d_in[6];
    const float* in_proj_w  = (const float*)d_in[7];
    const float* conv1d_w   = (const float*)d_in[8];
    const float* conv1d_b   = (const float*)d_in[9];
    const float* x_proj_w   = (const float*)d_in[10];
    const float* dt_proj_w  = (const float*)d_in[11];
    const float* dt_proj_b  = (const float*)d_in[12];
    const float* A_log      = (const float*)d_in[13];
    const float* Dp         = (const float*)d_in[14];
    const float* out_proj_w = (const float*)d_in[15];
    const float* fc1_w      = (const float*)d_in[16];
    const float* fc1_b      = (const float*)d_in[17];
    const float* fc2_w      = (const float*)d_in[18];
    const float* fc2_b      = (const float*)d_in[19];
    float* out = (float*)d_out;

    float *cbuf, *tcat, *xz, *xc, *xdbl, *y, *mo, *outssm, *lnbuf, *mid;
    cudaGetSymbolAddress((void**)&cbuf,   g_cbuf);
    cudaGetSymbolAddress((void**)&tcat,   g_tcat);
    cudaGetSymbolAddress((void**)&xz,     g_xz);
    cudaGetSymbolAddress((void**)&xc,     g_xc);
    cudaGetSymbolAddress((void**)&xdbl,   g_xdbl);
    cudaGetSymbolAddress((void**)&y,      g_y);
    cudaGetSymbolAddress((void**)&mo,     g_mo);
    cudaGetSymbolAddress((void**)&outssm, g_outssm);
    cudaGetSymbolAddress((void**)&lnbuf,  g_lnbuf);
    cudaGetSymbolAddress((void**)&mid,    g_mid);

    // 1) conv 1x3 both directions -> g_cbuf [4 seqs][16384][96]
    conv13_mma_kernel<0><<<256, 256>>>(x, conv1234_w, conv1234_b);
    conv13_mma_kernel<1><<<256, 256>>>(x, conv4321_w, conv4321_b);

    // 2) LN -> g_tcat (t1 stacked with t2, 65536 rows)
    ln_kernel<<<TTOK/8, 256>>>(cbuf, tcat, ln_g, ln_b, TTOK);

    // 3) in_proj: [65536,96] @ [384,96]^T -> g_xz
    {
        dim3 grid(TTOK/128, 4);
        gemm_tf32_kernel<0,false,false><<<grid, 256>>>(tcat, in_proj_w, nullptr, nullptr, xz, TTOK, 384, CCH);
    }

    // 4) depthwise conv1d + silu -> g_xc
    conv1d_kernel<<<(TTOK*DI)/256, 256>>>(xz, conv1d_w, conv1d_b);

    // 5) x_proj: [65536,192] @ [38,192]^T -> g_xdbl
    {
        dim3 grid(TTOK/128, 1);
        gemm_tf32_kernel<0,false,false><<<grid, 256>>>(xc, x_proj_w, nullptr, nullptr, xdbl, TTOK, NXD, DI);
    }

    // 6) dt projection + softplus -> g_dt
    dt_kernel<<<(TTOK*DI)/256, 256>>>(dt_proj_w, dt_proj_b);

    // 7-9) chunked selective scan
    scan1_kernel<<<NSEQ*NCH, 192>>>(A_log);
    scan2_kernel<<<(NSEQ*DI*DS)/256, 256>>>();
    scan3_kernel<<<NSEQ*NCH, 192>>>(A_log, Dp);

    // 10) out_proj: [65536,192] @ [96,192]^T -> g_mo
    {
        dim3 grid(TTOK/128, 1);
        gemm_tf32_kernel<0,false,false><<<grid, 256>>>(y, out_proj_w, nullptr, nullptr, mo, TTOK, CCH, DI);
    }

    // 11) out_ssm = mamba(t1)+mamba(t2)+t1+t2
    combine_kernel<<<(TOK2*CCH)/256, 256>>>();

    // 12) LN -> g_lnbuf
    ln_kernel<<<TOK2/8, 256>>>(outssm, lnbuf, ln_g, ln_b, TOK2);

    // 13) fc1 + gelu -> g_mid
    {
        dim3 grid(TOK2/128, 1);
        gemm_tf32_kernel<1,true,false><<<grid, 256>>>(lnbuf, fc1_w, fc1_b, nullptr, mid, TOK2, CCH, CCH);
    }

    // 14) fc2 + bias + residual(out_ssm) -> d_out
    {
        dim3 grid(TOK2/128, 1);
        gemm_tf32_kernel<0,true,true><<<grid, 256>>>(mid, fc2_w, fc2_b, outssm, out, TOK2, CCH, CCH);
    }
}